// round 17
// baseline (speedup 1.0000x reference)
#include <cuda_runtime.h>
#include <cuda_bf16.h>

#define NPIX 65536
#define CIN 128
#define NH 4
#define NT 4
#define OD 512
#define SCALE 0.08838834764831845f   // 1/sqrt(128)

// ---------------- global scratch ----------------
__device__ __align__(256) unsigned short g_bM[512 * 384];    // [o][k'] row-major [Hi|Hi|Lo]
__device__ __align__(256) unsigned short g_bP[128 * 1536];   // [d][k'] row-major [Hi|Hi|Lo]

// ---------------- helpers ----------------
__device__ __forceinline__ unsigned short bfs(float x) {
    __nv_bfloat16 h = __float2bfloat16(x);
    return *reinterpret_cast<unsigned short*>(&h);
}
__device__ __forceinline__ float bff(unsigned short u) {
    __nv_bfloat16 h = *reinterpret_cast<__nv_bfloat16*>(&u);
    return __bfloat162float(h);
}
__device__ __forceinline__ void cp16(unsigned dst_smem, const void* src) {
    asm volatile("cp.async.cg.shared.global [%0], [%1], 16;" :: "r"(dst_smem), "l"(src));
}
#define CP_COMMIT() asm volatile("cp.async.commit_group;")
#define CP_WAIT0()  asm volatile("cp.async.wait_group 0;")
#define CP_WAIT1()  asm volatile("cp.async.wait_group 1;")

#define LDSM4(r, addr) \
    asm volatile("ldmatrix.sync.aligned.m8n8.x4.shared.b16 {%0,%1,%2,%3}, [%4];" \
        : "=r"((r)[0]), "=r"((r)[1]), "=r"((r)[2]), "=r"((r)[3]) : "r"(addr))

#define MMA(c, a, b0, b1) \
    asm volatile("mma.sync.aligned.m16n8k16.row.col.f32.bf16.bf16.f32 " \
        "{%0,%1,%2,%3}, {%4,%5,%6,%7}, {%8,%9}, {%0,%1,%2,%3};" \
        : "+f"((c)[0]), "+f"((c)[1]), "+f"((c)[2]), "+f"((c)[3]) \
        : "r"((a)[0]), "r"((a)[1]), "r"((a)[2]), "r"((a)[3]), "r"(b0), "r"(b1))

// ---------------- kernel 1: fold weights (smem-staged, register-tiled) ----------------
// 8 blocks: blockIdx.x = task*4 + h. task 0: M' = Wq_h^T Wk_h ; task 1: P' = Wo_h Wv_h.
__global__ void __launch_bounds__(256)
fold_weights(const float* __restrict__ Wq, const float* __restrict__ Wk,
             const float* __restrict__ Wv, const float* __restrict__ Wo) {
    extern __shared__ float fs[];
    float* Am = fs;            // [64][128]
    float* Bm = fs + 8192;     // [64][128]
    const int tid = threadIdx.x;
    const int task = blockIdx.x >> 2, h = blockIdx.x & 3;

    #pragma unroll
    for (int i = 0; i < 32; i++) {
        int idx = tid + i * 256;
        int cc = idx >> 7, c = idx & 127;
        if (task == 0) {
            Am[idx] = Wq[(cc * 4 + h) * 128 + c];     // Am[cc][c1]
            Bm[idx] = Wk[(cc * 4 + h) * 128 + c];     // Bm[cc][c2]
        } else {
            Am[idx] = Wo[c * 256 + cc * 4 + h];       // Am[cc][d]
            Bm[idx] = Wv[(cc * 4 + h) * 128 + c];     // Bm[cc][c2]
        }
    }
    __syncthreads();

    const int ib = (tid >> 4) * 8, jb = (tid & 15) * 8;
    float acc[8][8];
    #pragma unroll
    for (int i = 0; i < 8; i++)
        #pragma unroll
        for (int j = 0; j < 8; j++) acc[i][j] = 0.f;

    for (int cc = 0; cc < 64; cc++) {
        float a[8], b[8];
        #pragma unroll
        for (int k = 0; k < 8; k++) { a[k] = Am[cc * 128 + ib + k]; b[k] = Bm[cc * 128 + jb + k]; }
        #pragma unroll
        for (int i = 0; i < 8; i++)
            #pragma unroll
            for (int j = 0; j < 8; j++) acc[i][j] = fmaf(a[i], b[j], acc[i][j]);
    }

    #pragma unroll
    for (int i = 0; i < 8; i++)
        #pragma unroll
        for (int j = 0; j < 8; j++) {
            float s = acc[i][j];
            unsigned short hi = bfs(s);
            unsigned short lo = bfs(s - bff(hi));
            if (task == 0) {
                int o = h * 128 + jb + j, c1 = ib + i;       // M'[o][k=c1]
                g_bM[(size_t)o * 384 + c1]       = hi;
                g_bM[(size_t)o * 384 + 128 + c1] = hi;
                g_bM[(size_t)o * 384 + 256 + c1] = lo;
            } else {
                int d = ib + i, o = h * 128 + jb + j;        // P'[d][k=o]
                g_bP[(size_t)d * 1536 + o]        = hi;
                g_bP[(size_t)d * 1536 + 512 + o]  = hi;
                g_bP[(size_t)d * 1536 + 1024 + o] = lo;
            }
        }
}

// ---------------- kernel 2 (fully fused): gemm1 -> softmax -> gemm2 ----------------
// Smem map (bytes):
//   [0, 50176)           phase A: z-split A image (64 x 784B, stride 392 bf16)
//                        phase C: two P' chunk buffers (128 x 144B each = 18432)
//   [50176, 197632)      phase A: M' double buffers (2 x 73728)
//                        phase B/C: U fp32 [64][516] then zbar bf16 image [64 x 2064B]
#define F_AST 392
#define F_ABYTES (64 * F_AST * 2)        // 50176
#define F_BBYTES (512 * 72 * 2)          // 73728
#define F_SMEM (F_ABYTES + 2 * F_BBYTES) // 197632
#define UST 516                          // fp32 stride; 2064B row = zbar image stride
#define PB_TB 18432                      // one 128 x 64k P' chunk (stride 144B)

__global__ void __launch_bounds__(512, 1)
fused(const float* __restrict__ z2d, const float* __restrict__ t2d,
      const float* __restrict__ bo, float* __restrict__ out) {
    extern __shared__ char smem[];
    char* As = smem;
    float* Us = (float*)(smem + F_ABYTES);
    const int tid = threadIdx.x, lane = tid & 31, wid = tid >> 5;
    const int p0 = blockIdx.x * 64;
    unsigned sbase = (unsigned)__cvta_generic_to_shared(smem);
    unsigned sA = sbase;
    unsigned sB0 = sbase + F_ABYTES;
    unsigned sUimg = sbase + F_ABYTES;      // 2064B-stride bf16 image (phase C A)

    // ---- build resident A = [Zhi | Zlo | Zhi] (64 px, K'=384) ----
    {
        const float* zsrc = z2d + (size_t)p0 * CIN;
        #pragma unroll
        for (int j = 0; j < 4; j++) {
            int u = tid + j * 512;
            int row = u >> 5, c = (u & 31) * 4;
            float4 v = *(const float4*)(zsrc + row * CIN + c);
            unsigned short h0 = bfs(v.x), h1 = bfs(v.y), h2 = bfs(v.z), h3 = bfs(v.w);
            unsigned short l0 = bfs(v.x - bff(h0)), l1 = bfs(v.y - bff(h1));
            unsigned short l2 = bfs(v.z - bff(h2)), l3 = bfs(v.w - bff(h3));
            uint2 hu = make_uint2((unsigned)h0 | ((unsigned)h1 << 16),
                                  (unsigned)h2 | ((unsigned)h3 << 16));
            uint2 lu = make_uint2((unsigned)l0 | ((unsigned)l1 << 16),
                                  (unsigned)l2 | ((unsigned)l3 << 16));
            *(uint2*)(As + row * (F_AST*2) + c * 2)         = hu;
            *(uint2*)(As + row * (F_AST*2) + (128 + c) * 2) = lu;
            *(uint2*)(As + row * (F_AST*2) + (256 + c) * 2) = hu;
        }
    }

    // prefetch M' chunk 0
    #pragma unroll
    for (int j = 0; j < 8; j++) {
        int i = tid + j * 512;
        int row = i >> 3, seg = i & 7;
        cp16(sB0 + row * 144 + seg * 16, g_bM + (size_t)row * 384 + seg * 8);
    }
    CP_COMMIT();

    // ---- phase A: U[64][512] = Zsplit @ M'^T ----
    {
        const int mw = wid & 1, nw = wid >> 1;   // 2m x 8n, warp tile 32x64
        float acc[2][8][4];
        #pragma unroll
        for (int a = 0; a < 2; a++)
            #pragma unroll
            for (int b = 0; b < 8; b++)
                #pragma unroll
                for (int q = 0; q < 4; q++) acc[a][b][q] = 0.f;

        for (int c = 0; c < 6; c++) {
            unsigned sBc = sB0 + (unsigned)(c & 1) * F_BBYTES;
            if (c < 5) {
                unsigned sBn = sB0 + (unsigned)((c + 1) & 1) * F_BBYTES;
                const unsigned short* src = g_bM + (c + 1) * 64;
                #pragma unroll
                for (int j = 0; j < 8; j++) {
                    int i = tid + j * 512;
                    int row = i >> 3, seg = i & 7;
                    cp16(sBn + row * 144 + seg * 16, src + (size_t)row * 384 + seg * 8);
                }
                CP_COMMIT();
                CP_WAIT1();
            } else {
                CP_WAIT0();
            }
            __syncthreads();
            #pragma unroll
            for (int ks = 0; ks < 4; ks++) {
                int kg = c * 64 + ks * 16;
                unsigned a[2][4];
                #pragma unroll
                for (int mf = 0; mf < 2; mf++) {
                    unsigned addr = sA + (mw * 32 + mf * 16 + (lane & 15)) * (F_AST*2)
                                       + (kg + (lane >> 4) * 8) * 2;
                    LDSM4(a[mf], addr);
                }
                #pragma unroll
                for (int nf2 = 0; nf2 < 4; nf2++) {
                    unsigned b[4];
                    int noff = nw * 64 + nf2 * 16 + (lane & 7) + ((lane >> 4) & 1) * 8;
                    unsigned baddr = sBc + noff * 144 + ks * 32 + ((lane >> 3) & 1) * 16;
                    LDSM4(b, baddr);
                    MMA(acc[0][nf2*2],   a[0], b[0], b[1]);
                    MMA(acc[0][nf2*2+1], a[0], b[2], b[3]);
                    MMA(acc[1][nf2*2],   a[1], b[0], b[1]);
                    MMA(acc[1][nf2*2+1], a[1], b[2], b[3]);
                }
            }
            __syncthreads();
        }

        // stage U into smem (overlays M' buffers — all reads done)
        #pragma unroll
        for (int mf = 0; mf < 2; mf++) {
            int row = mw * 32 + mf * 16 + (lane >> 2);
            #pragma unroll
            for (int nf = 0; nf < 8; nf++) {
                int col = nw * 64 + nf * 8 + (lane & 3) * 2;
                float* d0 = Us + (size_t)row * UST + col;
                *(float2*)d0             = make_float2(acc[mf][nf][0], acc[mf][nf][1]);
                *(float2*)(d0 + 8 * UST) = make_float2(acc[mf][nf][2], acc[mf][nf][3]);
            }
        }
    }

    // prefetch phase-C P' chunks 0 and 1 into As region (dead now) — rides under phase B
    #pragma unroll
    for (int cpre = 0; cpre < 2; cpre++) {
        unsigned sPB = sbase + (unsigned)cpre * PB_TB;
        const unsigned short* src = g_bP + cpre * 64;
        #pragma unroll
        for (int j = 0; j < 2; j++) {
            int i = tid + j * 512;          // 1024 cp16: row 0..127, seg 0..7
            int row = i >> 3, seg = i & 7;
            cp16(sPB + row * 144 + seg * 16, src + (size_t)row * 1536 + seg * 8);
        }
        CP_COMMIT();
    }
    __syncthreads();   // U visible to all

    // ---- phase B: scores, softmax over T, zbar -> bf16 [hi|lo] image over U (in place) ----
    {
        const int pix = (tid >> 5) * 4 + (lane & 3);   // 0..63
        const int sub = lane >> 2;                     // 0..7
        const int cb = sub * 16;
        const float* zt0 = t2d + (size_t)(p0 + pix) * CIN + cb;
        const float* Urow = Us + (size_t)pix * UST;

        // load t2d ONCE into registers
        float zlr[NT][16];
        #pragma unroll
        for (int t = 0; t < NT; t++)
            #pragma unroll
            for (int q4 = 0; q4 < 4; q4++) {
                float4 v = *(const float4*)(zt0 + (size_t)t * NPIX * CIN + q4 * 4);
                zlr[t][q4*4+0] = v.x; zlr[t][q4*4+1] = v.y;
                zlr[t][q4*4+2] = v.z; zlr[t][q4*4+3] = v.w;
            }

        float s[NT][NH];
        #pragma unroll
        for (int t = 0; t < NT; t++)
            #pragma unroll
            for (int h = 0; h < NH; h++) s[t][h] = 0.f;

        #pragma unroll
        for (int q4 = 0; q4 < 4; q4++)
            #pragma unroll
            for (int h = 0; h < NH; h++) {
                float4 u = *(const float4*)(Urow + h * 128 + cb + q4 * 4);
                #pragma unroll
                for (int t = 0; t < NT; t++)
                    s[t][h] += u.x * zlr[t][q4*4+0] + u.y * zlr[t][q4*4+1]
                             + u.z * zlr[t][q4*4+2] + u.w * zlr[t][q4*4+3];
            }
        #pragma unroll
        for (int t = 0; t < NT; t++)
            #pragma unroll
            for (int h = 0; h < NH; h++) {
                float p = s[t][h];
                p += __shfl_xor_sync(0xffffffffu, p, 4);
                p += __shfl_xor_sync(0xffffffffu, p, 8);
                p += __shfl_xor_sync(0xffffffffu, p, 16);
                s[t][h] = p * SCALE;
            }
        float w[NT][NH];
        #pragma unroll
        for (int h = 0; h < NH; h++) {
            float m = fmaxf(fmaxf(s[0][h], s[1][h]), fmaxf(s[2][h], s[3][h]));
            float e0 = __expf(s[0][h]-m), e1 = __expf(s[1][h]-m);
            float e2 = __expf(s[2][h]-m), e3 = __expf(s[3][h]-m);
            float inv = 1.f / (e0 + e1 + e2 + e3);
            w[0][h]=e0*inv; w[1][h]=e1*inv; w[2][h]=e2*inv; w[3][h]=e3*inv;
        }

        __syncthreads();   // ALL U reads complete before in-place overwrite

        char* imgrow = (char*)Us + (size_t)pix * 2064;
        #pragma unroll
        for (int h = 0; h < NH; h++) {
            unsigned hw[8], lw[8];
            #pragma unroll
            for (int j = 0; j < 8; j++) {
                float a = w[0][h]*zlr[0][2*j]   + w[1][h]*zlr[1][2*j]
                        + w[2][h]*zlr[2][2*j]   + w[3][h]*zlr[3][2*j];
                float b = w[0][h]*zlr[0][2*j+1] + w[1][h]*zlr[1][2*j+1]
                        + w[2][h]*zlr[2][2*j+1] + w[3][h]*zlr[3][2*j+1];
                unsigned short ha = bfs(a), hb = bfs(b);
                unsigned short la = bfs(a - bff(ha)), lb = bfs(b - bff(hb));
                hw[j] = (unsigned)ha | ((unsigned)hb << 16);
                lw[j] = (unsigned)la | ((unsigned)lb << 16);
            }
            int off_hi = (h * 128 + cb) * 2;
            *(uint4*)(imgrow + off_hi)          = make_uint4(hw[0], hw[1], hw[2], hw[3]);
            *(uint4*)(imgrow + off_hi + 16)     = make_uint4(hw[4], hw[5], hw[6], hw[7]);
            *(uint4*)(imgrow + 1024 + off_hi)      = make_uint4(lw[0], lw[1], lw[2], lw[3]);
            *(uint4*)(imgrow + 1024 + off_hi + 16) = make_uint4(lw[4], lw[5], lw[6], lw[7]);
        }
    }
    __syncthreads();   // zbar image visible

    // ---- phase C: out[64][128] = zbar' @ P'^T + bo ----
    // term schedule: c<8: A hi x B Hi ; c<16: A lo x B Hi(dup) ; c<24: A hi x B Lo
    {
        const int mw = wid & 3, nw = wid >> 2;   // 4m x 4n, warp tile 16x32
        float acc[4][4];
        #pragma unroll
        for (int b = 0; b < 4; b++)
            #pragma unroll
            for (int q = 0; q < 4; q++) acc[b][q] = 0.f;

        for (int c = 0; c < 24; c++) {
            if (c < 23) { CP_WAIT1(); } else { CP_WAIT0(); }
            __syncthreads();
            unsigned sBc = sbase + (unsigned)(c & 1) * PB_TB;
            int ao = (c < 8) ? c * 64 : (c < 16) ? 512 + (c - 8) * 64 : (c - 16) * 64;
            #pragma unroll
            for (int ks = 0; ks < 4; ks++) {
                unsigned a[4];
                unsigned aaddr = sUimg + (mw * 16 + (lane & 15)) * 2064
                                       + ao * 2 + ks * 32 + (lane >> 4) * 16;
                LDSM4(a, aaddr);
                #pragma unroll
                for (int nf2 = 0; nf2 < 2; nf2++) {
                    unsigned b[4];
                    int noff = nw * 32 + nf2 * 16 + (lane & 7) + ((lane >> 4) & 1) * 8;
                    unsigned baddr = sBc + noff * 144 + ks * 32 + ((lane >> 3) & 1) * 16;
                    LDSM4(b, baddr);
                    MMA(acc[nf2*2],   a, b[0], b[1]);
                    MMA(acc[nf2*2+1], a, b[2], b[3]);
                }
            }
            __syncthreads();
            if (c + 2 < 24) {
                unsigned sPB = sbase + (unsigned)(c & 1) * PB_TB;
                const unsigned short* src = g_bP + (c + 2) * 64;
                #pragma unroll
                for (int j = 0; j < 2; j++) {
                    int i = tid + j * 512;
                    int row = i >> 3, seg = i & 7;
                    cp16(sPB + row * 144 + seg * 16, src + (size_t)row * 1536 + seg * 8);
                }
                CP_COMMIT();
            }
        }

        // epilogue -> out + bo
        int row = p0 + mw * 16 + (lane >> 2);
        #pragma unroll
        for (int nf = 0; nf < 4; nf++) {
            int col = nw * 32 + nf * 8 + (lane & 3) * 2;
            float2 b2 = *(const float2*)(bo + col);
            float* d0 = out + (size_t)row * CIN + col;
            *(float2*)d0             = make_float2(acc[nf][0] + b2.x, acc[nf][1] + b2.y);
            *(float2*)(d0 + 8 * CIN) = make_float2(acc[nf][2] + b2.x, acc[nf][3] + b2.y);
        }
    }
}

// ---------------- launch ----------------
extern "C" void kernel_launch(void* const* d_in, const int* in_sizes, int n_in,
                              void* d_out, int out_size) {
    const float* z2d = (const float*)d_in[0];
    const float* t2d = (const float*)d_in[1];
    const float* Wq  = (const float*)d_in[2];
    const float* Wk  = (const float*)d_in[3];
    const float* Wv  = (const float*)d_in[4];
    const float* Wo  = (const float*)d_in[5];
    const float* bo  = (const float*)d_in[6];
    float* out = (float*)d_out;

    cudaFuncSetAttribute(fold_weights, cudaFuncAttributeMaxDynamicSharedMemorySize, 65536);
    cudaFuncSetAttribute(fused, cudaFuncAttributeMaxDynamicSharedMemorySize, F_SMEM);

    fold_weights<<<8, 256, 65536>>>(Wq, Wk, Wv, Wo);
    fused<<<NPIX / 64, 512, F_SMEM>>>(z2d, t2d, bo, out);
}